// round 1
// baseline (speedup 1.0000x reference)
#include <cuda_runtime.h>
#include <math.h>

#define B_ROWS 8192
#define D_IN   784
#define D_H    4096
#define D_OUT  10

#define THRESH 0.1f

// ---------------- scratch (no cudaMalloc allowed) ----------------
__device__ float        g_h[(size_t)B_ROWS * D_H];   // relu'd hidden acts, fp32
__device__ unsigned int g_maxbits;                   // float bits of max (non-negative)

__global__ void init_kernel() { g_maxbits = 0u; }

// ---------------- kernel 1: h = relu(x @ tern(w1)^T + b1), track max ----------------
#define BM 128
#define BN 128
#define BK 16
#define TM 8
#define TN 8
// 256 threads, each computes an 8x8 micro-tile.

__device__ __forceinline__ float ternf(float v) {
    return (v > THRESH) ? 1.0f : ((v < -THRESH) ? -1.0f : 0.0f);
}

__global__ __launch_bounds__(256, 2) void gemm1_kernel(
    const float* __restrict__ x,
    const float* __restrict__ w1,
    const float* __restrict__ b1)
{
    __shared__ float As[BK][BM];  // [k][m]
    __shared__ float Bs[BK][BN];  // [k][n] (ternarized)

    const int tid = threadIdx.x;
    const int bm  = blockIdx.y * BM;
    const int bn  = blockIdx.x * BN;
    const int ty  = tid >> 4;    // 0..15
    const int tx  = tid & 15;    // 0..15

    float acc[TM][TN];
#pragma unroll
    for (int i = 0; i < TM; i++)
#pragma unroll
        for (int j = 0; j < TN; j++) acc[i][j] = 0.0f;

    // K = 784 = 49 * 16, always exact
    for (int k0 = 0; k0 < D_IN; k0 += BK) {
        // load A tile: 128 rows x 16 k = 512 float4, 2 per thread
#pragma unroll
        for (int r = 0; r < 2; r++) {
            int i   = tid + r * 256;      // float4 id 0..511
            int row = i >> 2;             // 0..127
            int kq  = (i & 3) << 2;       // 0,4,8,12
            float4 v = *(const float4*)&x[(size_t)(bm + row) * D_IN + k0 + kq];
            As[kq + 0][row] = v.x;
            As[kq + 1][row] = v.y;
            As[kq + 2][row] = v.z;
            As[kq + 3][row] = v.w;
        }
        // load B tile (w1 rows bn..bn+127), ternarize on store
#pragma unroll
        for (int r = 0; r < 2; r++) {
            int i   = tid + r * 256;
            int row = i >> 2;
            int kq  = (i & 3) << 2;
            float4 v = *(const float4*)&w1[(size_t)(bn + row) * D_IN + k0 + kq];
            Bs[kq + 0][row] = ternf(v.x);
            Bs[kq + 1][row] = ternf(v.y);
            Bs[kq + 2][row] = ternf(v.z);
            Bs[kq + 3][row] = ternf(v.w);
        }
        __syncthreads();

#pragma unroll
        for (int kk = 0; kk < BK; kk++) {
            float a[TM], b[TN];
            // vector smem loads (32B aligned)
            float4 a0 = *(const float4*)&As[kk][ty * TM + 0];
            float4 a1 = *(const float4*)&As[kk][ty * TM + 4];
            float4 b0 = *(const float4*)&Bs[kk][tx * TN + 0];
            float4 b1v = *(const float4*)&Bs[kk][tx * TN + 4];
            a[0]=a0.x; a[1]=a0.y; a[2]=a0.z; a[3]=a0.w;
            a[4]=a1.x; a[5]=a1.y; a[6]=a1.z; a[7]=a1.w;
            b[0]=b0.x; b[1]=b0.y; b[2]=b0.z; b[3]=b0.w;
            b[4]=b1v.x; b[5]=b1v.y; b[6]=b1v.z; b[7]=b1v.w;
#pragma unroll
            for (int i = 0; i < TM; i++)
#pragma unroll
                for (int j = 0; j < TN; j++)
                    acc[i][j] = fmaf(a[i], b[j], acc[i][j]);
        }
        __syncthreads();
    }

    // epilogue: bias + relu + store + local max
    float lmax = 0.0f;
#pragma unroll
    for (int i = 0; i < TM; i++) {
        int row = bm + ty * TM + i;
        float* hrow = &g_h[(size_t)row * D_H + bn + tx * TN];
#pragma unroll
        for (int j = 0; j < TN; j++) {
            float v = acc[i][j] + b1[bn + tx * TN + j];
            v = fmaxf(v, 0.0f);
            hrow[j] = v;
            lmax = fmaxf(lmax, v);
        }
    }

    // warp max -> block max -> one atomic
#pragma unroll
    for (int off = 16; off > 0; off >>= 1)
        lmax = fmaxf(lmax, __shfl_xor_sync(0xffffffffu, lmax, off));
    __shared__ float wmax[8];
    int lane = tid & 31, warp = tid >> 5;
    if (lane == 0) wmax[warp] = lmax;
    __syncthreads();
    if (tid == 0) {
        float m = wmax[0];
#pragma unroll
        for (int w = 1; w < 8; w++) m = fmaxf(m, wmax[w]);
        atomicMax(&g_maxbits, __float_as_uint(m));  // valid: values >= 0
    }
}

// ---------------- kernel 2: quant + layer2 + log_softmax ----------------
// one warp per output row; ternarized w2 in smem as int8.
__global__ __launch_bounds__(256) void layer2_kernel(
    const float* __restrict__ w2,
    const float* __restrict__ b2,
    float* __restrict__ out)
{
    __shared__ signed char ws[D_OUT * D_H];  // 40 KB
    __shared__ float s_b2[16];

    const int tid = threadIdx.x;
    for (int i = tid; i < D_OUT * D_H; i += 256) {
        float v = w2[i];
        ws[i] = (v > THRESH) ? (signed char)1 : ((v < -THRESH) ? (signed char)-1 : (signed char)0);
    }
    if (tid < D_OUT) s_b2[tid] = b2[tid];
    __syncthreads();

    const float maxv  = __uint_as_float(g_maxbits);
    const float scale = 127.0f / maxv;

    const int lane = tid & 31, warp = tid >> 5;
    const int row  = blockIdx.x * 8 + warp;

    const float4* hrow = (const float4*)(g_h + (size_t)row * D_H);

    float acc[D_OUT];
#pragma unroll
    for (int c = 0; c < D_OUT; c++) acc[c] = 0.0f;

    for (int it = lane; it < D_H / 4; it += 32) {
        float4 h4 = hrow[it];
        // h >= 0 after relu; clip upper side only (lower clip is a no-op)
        float q0 = fminf(rintf(h4.x * scale), 127.0f);
        float q1 = fminf(rintf(h4.y * scale), 127.0f);
        float q2 = fminf(rintf(h4.z * scale), 127.0f);
        float q3 = fminf(rintf(h4.w * scale), 127.0f);
        int kb = it * 4;
#pragma unroll
        for (int c = 0; c < D_OUT; c++) {
            const signed char* wr = &ws[c * D_H + kb];
            acc[c] = fmaf(q0, (float)wr[0], acc[c]);
            acc[c] = fmaf(q1, (float)wr[1], acc[c]);
            acc[c] = fmaf(q2, (float)wr[2], acc[c]);
            acc[c] = fmaf(q3, (float)wr[3], acc[c]);
        }
    }

    // warp reduce (sums are exact integers < 2^24, order-independent)
#pragma unroll
    for (int off = 16; off > 0; off >>= 1)
#pragma unroll
        for (int c = 0; c < D_OUT; c++)
            acc[c] += __shfl_xor_sync(0xffffffffu, acc[c], off);

    if (lane == 0) {
        float l[D_OUT];
        float m = -1e30f;
#pragma unroll
        for (int c = 0; c < D_OUT; c++) {
            l[c] = acc[c] / scale + s_b2[c];
            m = fmaxf(m, l[c]);
        }
        float s = 0.0f;
#pragma unroll
        for (int c = 0; c < D_OUT; c++) s += expf(l[c] - m);
        float lse = m + logf(s);
        float* orow = out + (size_t)row * D_OUT;
#pragma unroll
        for (int c = 0; c < D_OUT; c++) orow[c] = l[c] - lse;
    }
}

// ---------------- launch ----------------
extern "C" void kernel_launch(void* const* d_in, const int* in_sizes, int n_in,
                              void* d_out, int out_size)
{
    const float* x  = (const float*)d_in[0];
    const float* w1 = (const float*)d_in[1];
    const float* b1 = (const float*)d_in[2];
    const float* w2 = (const float*)d_in[3];
    const float* b2 = (const float*)d_in[4];
    float* out = (float*)d_out;

    init_kernel<<<1, 1>>>();

    dim3 g1(D_H / BN, B_ROWS / BM);  // (32, 64)
    gemm1_kernel<<<g1, 256>>>(x, w1, b1);

    layer2_kernel<<<B_ROWS / 8, 256>>>(w2, b2, out);
}

// round 6
// speedup vs baseline: 3.6294x; 3.6294x over previous
#include <cuda_runtime.h>
#include <cuda_fp16.h>
#include <math.h>
#include <stdint.h>

#define B_ROWS 8192
#define D_IN   784
#define D_H    4096
#define D_OUT  10
#define THRESH 0.1f

#define KPAD   832          // 784 padded to 26*32
#define KITER  26           // K chunks of 32 halves
#define NST    4            // cp.async pipeline stages

// ---------------- device scratch ----------------
__device__ __half g_xhi[(size_t)B_ROWS * KPAD];
__device__ __half g_xlo[(size_t)B_ROWS * KPAD];
__device__ __half g_w1h[(size_t)D_H * KPAD];
__device__ float  g_h[(size_t)B_ROWS * D_H];
__device__ unsigned int g_maxbits;

// ---------------- helpers ----------------
__device__ __forceinline__ uint32_t smem_to_u32(const void* p) {
    uint32_t a;
    asm("{ .reg .u64 t; cvta.to.shared.u64 t, %1; cvt.u32.u64 %0, t; }" : "=r"(a) : "l"(p));
    return a;
}
__device__ __forceinline__ void cp16(uint32_t s, const void* g) {
    asm volatile("cp.async.cg.shared.global [%0], [%1], 16;" :: "r"(s), "l"(g));
}
__device__ __forceinline__ void ldsm_x4(uint32_t* r, uint32_t addr) {
    asm volatile("ldmatrix.sync.aligned.m8n8.x4.shared.b16 {%0,%1,%2,%3}, [%4];"
        : "=r"(r[0]), "=r"(r[1]), "=r"(r[2]), "=r"(r[3]) : "r"(addr));
}
__device__ __forceinline__ void mma16816(float* c, const uint32_t* a, const uint32_t* b) {
    asm volatile(
        "mma.sync.aligned.m16n8k16.row.col.f32.f16.f16.f32 "
        "{%0,%1,%2,%3}, {%4,%5,%6,%7}, {%8,%9}, {%0,%1,%2,%3};"
        : "+f"(c[0]), "+f"(c[1]), "+f"(c[2]), "+f"(c[3])
        : "r"(a[0]), "r"(a[1]), "r"(a[2]), "r"(a[3]), "r"(b[0]), "r"(b[1]));
}

__device__ __forceinline__ float ternf(float v) {
    return (v > THRESH) ? 1.0f : ((v < -THRESH) ? -1.0f : 0.0f);
}

// ---------------- prep kernels ----------------
__global__ void prep_x_kernel(const float* __restrict__ x) {
    int g = blockIdx.x * 256 + threadIdx.x;        // group of 8 elements
    if (g == 0) g_maxbits = 0u;
    int row = g / 104, part = g - row * 104;       // 104 groups of 8 = 832
    __align__(16) __half hh[8];
    __align__(16) __half ll[8];
    if (part < 98) {
        const float4* p = (const float4*)(x + (size_t)row * D_IN + part * 8);
        float4 a = p[0], b = p[1];
        float v[8] = {a.x, a.y, a.z, a.w, b.x, b.y, b.z, b.w};
#pragma unroll
        for (int i = 0; i < 8; i++) {
            __half h = __float2half_rn(v[i]);
            float r = v[i] - __half2float(h);
            hh[i] = h;
            ll[i] = __float2half_rn(r);
        }
    } else {
#pragma unroll
        for (int i = 0; i < 8; i++) { hh[i] = __ushort_as_half(0); ll[i] = __ushort_as_half(0); }
    }
    *(uint4*)(g_xhi + (size_t)g * 8) = *(uint4*)hh;
    *(uint4*)(g_xlo + (size_t)g * 8) = *(uint4*)ll;
}

__global__ void prep_w1_kernel(const float* __restrict__ w1) {
    int g = blockIdx.x * 256 + threadIdx.x;
    int row = g / 104, part = g - row * 104;
    __align__(16) __half hh[8];
    if (part < 98) {
        const float4* p = (const float4*)(w1 + (size_t)row * D_IN + part * 8);
        float4 a = p[0], b = p[1];
        float v[8] = {a.x, a.y, a.z, a.w, b.x, b.y, b.z, b.w};
#pragma unroll
        for (int i = 0; i < 8; i++) hh[i] = __float2half_rn(ternf(v[i]));
    } else {
#pragma unroll
        for (int i = 0; i < 8; i++) hh[i] = __ushort_as_half(0);
    }
    *(uint4*)(g_w1h + (size_t)g * 8) = *(uint4*)hh;
}

// ---------------- gemm1: legacy HMMA (mma.sync) M128 x N128, hi/lo fp16 split ----------------
// Per-stage smem: A_hi 8KB | A_lo 8KB | B 8KB = 24KB; 4 stages = 96KB; bias 512B.
#define STAGE    24576
#define OFF_ALO  8192
#define OFF_B    16384
#define OFF_BIAS (STAGE * NST)          // 98304
#define SMEM_REQ (OFF_BIAS + 512)

__global__ void __launch_bounds__(256, 2) gemm1_mma_kernel(const float* __restrict__ b1) {
    extern __shared__ char smem_raw[];
    const uint32_t sb = smem_to_u32(smem_raw);
    float* s_bias = (float*)(smem_raw + OFF_BIAS);

    const int tid    = threadIdx.x;
    const int lane   = tid & 31;
    const int wid    = tid >> 5;
    const int warp_m = wid & 3;          // 4 warps over M (32 rows each)
    const int warp_n = wid >> 2;         // 2 warps over N (64 cols each)
    const int bm = blockIdx.y * 128;
    const int bn = blockIdx.x * 128;

    if (tid < 128) s_bias[tid] = b1[bn + tid];

    // ---- per-thread cp.async source/dest precompute (2 x 16B per array per stage) ----
    size_t   a_goff[2], b_goff[2];
    uint32_t sw_off[2];
#pragma unroll
    for (int j = 0; j < 2; j++) {
        int idx = tid + j * 256;          // 0..511
        int row = idx >> 2;               // 0..127
        int ch  = idx & 3;                // 16B chunk within 64B row
        sw_off[j] = (uint32_t)(row * 64 + ((ch ^ ((row >> 1) & 3)) << 4));
        a_goff[j] = (size_t)(bm + row) * KPAD + ch * 8;
        b_goff[j] = (size_t)(bn + row) * KPAD + ch * 8;
    }

    // ---- ldmatrix address precompute ----
    // A (and A_lo): x4 -> m0:rows0-7/k0-7, m1:rows8-15/k0-7, m2:rows0-7/k8-15, m3:rows8-15/k8-15
    const int a_row = warp_m * 32 + (lane & 15);
    const int a_sel = (a_row >> 1) & 3;
    uint32_t a_base[2];
#pragma unroll
    for (int kk = 0; kk < 2; kk++)
        a_base[kk] = (uint32_t)(a_row * 64 + (((kk * 2 + (lane >> 4)) ^ a_sel) << 4));
    // B: x4 -> m0:n0-7/k0-7, m1:n0-7/k8-15, m2:n8-15/k0-7, m3:n8-15/k8-15
    const int n_off = ((lane >> 4) & 1) * 8 + (lane & 7);
    const int cpar  = (lane >> 3) & 1;
    const int b_row = warp_n * 64 + n_off;
    const int b_sel = (b_row >> 1) & 3;
    uint32_t b_base[2];
#pragma unroll
    for (int kk = 0; kk < 2; kk++)
        b_base[kk] = (uint32_t)(b_row * 64 + (((kk * 2 + cpar) ^ b_sel) << 4));

    float acc[2][8][4];
#pragma unroll
    for (int mt = 0; mt < 2; mt++)
#pragma unroll
        for (int nt = 0; nt < 8; nt++)
#pragma unroll
            for (int r = 0; r < 4; r++) acc[mt][nt][r] = 0.0f;

    // ---- prologue: stages 0..2 ----
#pragma unroll
    for (int s = 0; s < NST - 1; s++) {
        const uint32_t st = sb + s * STAGE;
        const int k0 = s * 32;
#pragma unroll
        for (int j = 0; j < 2; j++) {
            cp16(st + sw_off[j],           g_xhi + a_goff[j] + k0);
            cp16(st + OFF_ALO + sw_off[j], g_xlo + a_goff[j] + k0);
            cp16(st + OFF_B + sw_off[j],   g_w1h + b_goff[j] + k0);
        }
        asm volatile("cp.async.commit_group;");
    }

    // ---- mainloop ----
    int fetch = NST - 1;
#pragma unroll 1
    for (int c = 0; c < KITER; c++) {
        asm volatile("cp.async.wait_group 2;");
        __syncthreads();

        if (fetch < KITER) {
            const uint32_t st = sb + (fetch & 3) * STAGE;
            const int k0 = fetch * 32;
#pragma unroll
            for (int j = 0; j < 2; j++) {
                cp16(st + sw_off[j],           g_xhi + a_goff[j] + k0);
                cp16(st + OFF_ALO + sw_off[j], g_xlo + a_goff[j] + k0);
                cp16(st + OFF_B + sw_off[j],   g_w1h + b_goff[j] + k0);
            }
        }
        asm volatile("cp.async.commit_group;");
        fetch++;

        const uint32_t st = sb + (c & 3) * STAGE;
#pragma unroll
        for (int kk = 0; kk < 2; kk++) {
            uint32_t ah[2][4], al[2][4], bfr[4][4];
#pragma unroll
            for (int mt = 0; mt < 2; mt++) {
                ldsm_x4(ah[mt], st + a_base[kk] + mt * 1024);
                ldsm_x4(al[mt], st + OFF_ALO + a_base[kk] + mt * 1024);
            }
#pragma unroll
            for (int nt2 = 0; nt2 < 4; nt2++)
                ldsm_x4(bfr[nt2], st + OFF_B + b_base[kk] + nt2 * 1024);
#pragma unroll
            for (int mt = 0; mt < 2; mt++)
#pragma unroll
                for (int nt = 0; nt < 8; nt++) {
                    const uint32_t* bp2 = &bfr[nt >> 1][(nt & 1) * 2];
                    mma16816(acc[mt][nt], ah[mt], bp2);
                    mma16816(acc[mt][nt], al[mt], bp2);
                }
        }
    }

    // ---- epilogue: bias + relu + store + max ----
    __shared__ float wmax[8];
    const int qrow  = lane >> 2;
    const int qcol2 = (lane & 3) * 2;
    float lmax = 0.0f;
#pragma unroll
    for (int mt = 0; mt < 2; mt++) {
#pragma unroll
        for (int nt = 0; nt < 8; nt++) {
            const int nl = warp_n * 64 + nt * 8 + qcol2;
            const int m0 = bm + warp_m * 32 + mt * 16 + qrow;
            const float bb0 = s_bias[nl], bb1 = s_bias[nl + 1];
            float v0 = fmaxf(acc[mt][nt][0] + bb0, 0.0f);
            float v1 = fmaxf(acc[mt][nt][1] + bb1, 0.0f);
            float v2 = fmaxf(acc[mt][nt][2] + bb0, 0.0f);
            float v3 = fmaxf(acc[mt][nt][3] + bb1, 0.0f);
            lmax = fmaxf(fmaxf(lmax, fmaxf(v0, v1)), fmaxf(v2, v3));
            float2 p0 = make_float2(v0, v1);
            float2 p1 = make_float2(v2, v3);
            *(float2*)(g_h + (size_t)m0 * D_H + bn + nl)       = p0;
            *(float2*)(g_h + (size_t)(m0 + 8) * D_H + bn + nl) = p1;
        }
    }
#pragma unroll
    for (int off = 16; off > 0; off >>= 1)
        lmax = fmaxf(lmax, __shfl_xor_sync(0xffffffffu, lmax, off));
    if (lane == 0) wmax[wid] = lmax;
    __syncthreads();
    if (tid == 0) {
        float m = wmax[0];
#pragma unroll
        for (int i = 1; i < 8; i++) m = fmaxf(m, wmax[i]);
        atomicMax(&g_maxbits, __float_as_uint(m));
    }
}

// ---------------- kernel 2: quant + layer2 + log_softmax (unchanged, known-good) ----------------
__global__ __launch_bounds__(256) void layer2_kernel(
    const float* __restrict__ w2,
    const float* __restrict__ b2,
    float* __restrict__ out)
{
    __shared__ signed char ws[D_OUT * D_H];  // 40 KB
    __shared__ float s_b2[16];

    const int tid = threadIdx.x;
    for (int i = tid; i < D_OUT * D_H; i += 256) {
        float v = w2[i];
        ws[i] = (v > THRESH) ? (signed char)1 : ((v < -THRESH) ? (signed char)-1 : (signed char)0);
    }
    if (tid < D_OUT) s_b2[tid] = b2[tid];
    __syncthreads();

    const float maxv  = __uint_as_float(g_maxbits);
    const float scale = 127.0f / maxv;

    const int lane = tid & 31, warp = tid >> 5;
    const int row  = blockIdx.x * 8 + warp;

    const float4* hrow = (const float4*)(g_h + (size_t)row * D_H);

    float acc[D_OUT];
#pragma unroll
    for (int c = 0; c < D_OUT; c++) acc[c] = 0.0f;

    for (int it = lane; it < D_H / 4; it += 32) {
        float4 h4 = hrow[it];
        float q0 = fminf(rintf(h4.x * scale), 127.0f);
        float q1 = fminf(rintf(h4.y * scale), 127.0f);
        float q2 = fminf(rintf(h4.z * scale), 127.0f);
        float q3 = fminf(rintf(h4.w * scale), 127.0f);
        int kb = it * 4;
#pragma unroll
        for (int c = 0; c < D_OUT; c++) {
            const signed char* wr = &ws[c * D_H + kb];
            acc[c] = fmaf(q0, (float)wr[0], acc[c]);
            acc[c] = fmaf(q1, (float)wr[1], acc[c]);
            acc[c] = fmaf(q2, (float)wr[2], acc[c]);
            acc[c] = fmaf(q3, (float)wr[3], acc[c]);
        }
    }

#pragma unroll
    for (int off = 16; off > 0; off >>= 1)
#pragma unroll
        for (int c = 0; c < D_OUT; c++)
            acc[c] += __shfl_xor_sync(0xffffffffu, acc[c], off);

    if (lane == 0) {
        float l[D_OUT];
        float m = -1e30f;
#pragma unroll
        for (int c = 0; c < D_OUT; c++) {
            l[c] = acc[c] / scale + s_b2[c];
            m = fmaxf(m, l[c]);
        }
        float s = 0.0f;
#pragma unroll
        for (int c = 0; c < D_OUT; c++) s += expf(l[c] - m);
        float lse = m + logf(s);
        float* orow = out + (size_t)row * D_OUT;
#pragma unroll
        for (int c = 0; c < D_OUT; c++) orow[c] = l[c] - lse;
    }
}

// ---------------- launch ----------------
extern "C" void kernel_launch(void* const* d_in, const int* in_sizes, int n_in,
                              void* d_out, int out_size)
{
    const float* x  = (const float*)d_in[0];
    const float* w1 = (const float*)d_in[1];
    const float* b1 = (const float*)d_in[2];
    const float* w2 = (const float*)d_in[3];
    const float* b2 = (const float*)d_in[4];
    float* out = (float*)d_out;

    cudaFuncSetAttribute(gemm1_mma_kernel, cudaFuncAttributeMaxDynamicSharedMemorySize, SMEM_REQ);

    prep_x_kernel<<<(B_ROWS * 104) / 256, 256>>>(x);     // also resets g_maxbits
    prep_w1_kernel<<<(D_H * 104) / 256, 256>>>(w1);

    dim3 g1(D_H / 128, B_ROWS / 128);  // (32, 64)
    gemm1_mma_kernel<<<g1, 256, SMEM_REQ>>>(b1);

    layer2_kernel<<<B_ROWS / 8, 256>>>(w2, b2, out);
}

// round 8
// speedup vs baseline: 4.3401x; 1.1958x over previous
#include <cuda_runtime.h>
#include <cuda_fp16.h>
#include <math.h>
#include <stdint.h>

#define B_ROWS 8192
#define D_IN   784
#define D_H    4096
#define D_OUT  10
#define THRESH 0.1f

#define KPAD   832          // 784 padded to 26*32
#define KITER  26           // K chunks of 32 halves
#define NST    4            // cp.async pipeline stages

// ---------------- device scratch ----------------
__device__ __half g_xhi[(size_t)B_ROWS * KPAD];
__device__ __half g_xlo[(size_t)B_ROWS * KPAD];
__device__ __half g_w1h[(size_t)D_H * KPAD];
__device__ float  g_h[(size_t)B_ROWS * D_H];
__device__ int    g_w2q[D_OUT * (D_H / 4)];     // packed int8 ternary w2
__device__ unsigned int g_maxbits;

// ---------------- helpers ----------------
__device__ __forceinline__ uint32_t smem_to_u32(const void* p) {
    uint32_t a;
    asm("{ .reg .u64 t; cvta.to.shared.u64 t, %1; cvt.u32.u64 %0, t; }" : "=r"(a) : "l"(p));
    return a;
}
__device__ __forceinline__ void cp16(uint32_t s, const void* g) {
    asm volatile("cp.async.cg.shared.global [%0], [%1], 16;" :: "r"(s), "l"(g));
}
__device__ __forceinline__ void ldsm_x4(uint32_t* r, uint32_t addr) {
    asm volatile("ldmatrix.sync.aligned.m8n8.x4.shared.b16 {%0,%1,%2,%3}, [%4];"
        : "=r"(r[0]), "=r"(r[1]), "=r"(r[2]), "=r"(r[3]) : "r"(addr));
}
__device__ __forceinline__ void mma16816(float* c, const uint32_t* a, const uint32_t* b) {
    asm volatile(
        "mma.sync.aligned.m16n8k16.row.col.f32.f16.f16.f32 "
        "{%0,%1,%2,%3}, {%4,%5,%6,%7}, {%8,%9}, {%0,%1,%2,%3};"
        : "+f"(c[0]), "+f"(c[1]), "+f"(c[2]), "+f"(c[3])
        : "r"(a[0]), "r"(a[1]), "r"(a[2]), "r"(a[3]), "r"(b[0]), "r"(b[1]));
}
__device__ __forceinline__ int dp4a_s(int a, int b, int c) {
    int d;
    asm("dp4a.s32.s32 %0, %1, %2, %3;" : "=r"(d) : "r"(a), "r"(b), "r"(c));
    return d;
}

__device__ __forceinline__ float ternf(float v) {
    return (v > THRESH) ? 1.0f : ((v < -THRESH) ? -1.0f : 0.0f);
}
__device__ __forceinline__ int terni(float v) {
    return (v > THRESH) ? 1 : ((v < -THRESH) ? -1 : 0);
}

// ---------------- prep kernels ----------------
__global__ void prep_x_kernel(const float* __restrict__ x) {
    int g = blockIdx.x * 256 + threadIdx.x;        // group of 8 elements
    if (g == 0) g_maxbits = 0u;
    int row = g / 104, part = g - row * 104;       // 104 groups of 8 = 832
    __align__(16) __half hh[8];
    __align__(16) __half ll[8];
    if (part < 98) {
        const float4* p = (const float4*)(x + (size_t)row * D_IN + part * 8);
        float4 a = p[0], b = p[1];
        float v[8] = {a.x, a.y, a.z, a.w, b.x, b.y, b.z, b.w};
#pragma unroll
        for (int i = 0; i < 8; i++) {
            __half h = __float2half_rn(v[i]);
            float r = v[i] - __half2float(h);
            hh[i] = h;
            ll[i] = __float2half_rn(r);
        }
    } else {
#pragma unroll
        for (int i = 0; i < 8; i++) { hh[i] = __ushort_as_half(0); ll[i] = __ushort_as_half(0); }
    }
    *(uint4*)(g_xhi + (size_t)g * 8) = *(uint4*)hh;
    *(uint4*)(g_xlo + (size_t)g * 8) = *(uint4*)ll;
}

// blocks [0, 1664): ternarize w1 -> fp16. block 1664: pack ternary w2 -> int8x4.
__global__ void prep_w_kernel(const float* __restrict__ w1, const float* __restrict__ w2) {
    if (blockIdx.x < (D_H * 104) / 256) {
        int g = blockIdx.x * 256 + threadIdx.x;
        int row = g / 104, part = g - row * 104;
        __align__(16) __half hh[8];
        if (part < 98) {
            const float4* p = (const float4*)(w1 + (size_t)row * D_IN + part * 8);
            float4 a = p[0], b = p[1];
            float v[8] = {a.x, a.y, a.z, a.w, b.x, b.y, b.z, b.w};
#pragma unroll
            for (int i = 0; i < 8; i++) hh[i] = __float2half_rn(ternf(v[i]));
        } else {
#pragma unroll
            for (int i = 0; i < 8; i++) hh[i] = __ushort_as_half(0);
        }
        *(uint4*)(g_w1h + (size_t)g * 8) = *(uint4*)hh;
    } else {
        // pack w2: 10*1024 words, 256 threads -> 40 iters
        for (int i = threadIdx.x; i < D_OUT * (D_H / 4); i += 256) {
            const float4 v = *(const float4*)(w2 + (size_t)i * 4);
            uint32_t p = (uint32_t)(terni(v.x) & 0xff)
                       | ((uint32_t)(terni(v.y) & 0xff) << 8)
                       | ((uint32_t)(terni(v.z) & 0xff) << 16)
                       | ((uint32_t)(terni(v.w) & 0xff) << 24);
            g_w2q[i] = (int)p;
        }
    }
}

// ---------------- gemm1: legacy HMMA (mma.sync) M128 x N128, hi/lo fp16 split ----------------
// Per-stage smem: A_hi 8KB | A_lo 8KB | B 8KB = 24KB; 4 stages = 96KB; bias 512B.
#define STAGE    24576
#define OFF_ALO  8192
#define OFF_B    16384
#define OFF_BIAS (STAGE * NST)          // 98304
#define SMEM_REQ (OFF_BIAS + 512)

__global__ void __launch_bounds__(256, 2) gemm1_mma_kernel(const float* __restrict__ b1) {
    extern __shared__ char smem_raw[];
    const uint32_t sb = smem_to_u32(smem_raw);
    float* s_bias = (float*)(smem_raw + OFF_BIAS);

    const int tid    = threadIdx.x;
    const int lane   = tid & 31;
    const int wid    = tid >> 5;
    const int warp_m = wid & 3;          // 4 warps over M (32 rows each)
    const int warp_n = wid >> 2;         // 2 warps over N (64 cols each)
    const int bm = blockIdx.y * 128;
    const int bn = blockIdx.x * 128;

    if (tid < 128) s_bias[tid] = b1[bn + tid];

    // ---- per-thread cp.async source/dest precompute (2 x 16B per array per stage) ----
    size_t   a_goff[2], b_goff[2];
    uint32_t sw_off[2];
#pragma unroll
    for (int j = 0; j < 2; j++) {
        int idx = tid + j * 256;          // 0..511
        int row = idx >> 2;               // 0..127
        int ch  = idx & 3;                // 16B chunk within 64B row
        sw_off[j] = (uint32_t)(row * 64 + ((ch ^ ((row >> 1) & 3)) << 4));
        a_goff[j] = (size_t)(bm + row) * KPAD + ch * 8;
        b_goff[j] = (size_t)(bn + row) * KPAD + ch * 8;
    }

    // ---- ldmatrix address precompute ----
    const int a_row = warp_m * 32 + (lane & 15);
    const int a_sel = (a_row >> 1) & 3;
    uint32_t a_base[2];
#pragma unroll
    for (int kk = 0; kk < 2; kk++)
        a_base[kk] = (uint32_t)(a_row * 64 + (((kk * 2 + (lane >> 4)) ^ a_sel) << 4));
    const int n_off = ((lane >> 4) & 1) * 8 + (lane & 7);
    const int cpar  = (lane >> 3) & 1;
    const int b_row = warp_n * 64 + n_off;
    const int b_sel = (b_row >> 1) & 3;
    uint32_t b_base[2];
#pragma unroll
    for (int kk = 0; kk < 2; kk++)
        b_base[kk] = (uint32_t)(b_row * 64 + (((kk * 2 + cpar) ^ b_sel) << 4));

    float acc[2][8][4];
#pragma unroll
    for (int mt = 0; mt < 2; mt++)
#pragma unroll
        for (int nt = 0; nt < 8; nt++)
#pragma unroll
            for (int r = 0; r < 4; r++) acc[mt][nt][r] = 0.0f;

    // ---- prologue ----
#pragma unroll
    for (int s = 0; s < NST - 1; s++) {
        const uint32_t st = sb + s * STAGE;
        const int k0 = s * 32;
#pragma unroll
        for (int j = 0; j < 2; j++) {
            cp16(st + sw_off[j],           g_xhi + a_goff[j] + k0);
            cp16(st + OFF_ALO + sw_off[j], g_xlo + a_goff[j] + k0);
            cp16(st + OFF_B + sw_off[j],   g_w1h + b_goff[j] + k0);
        }
        asm volatile("cp.async.commit_group;");
    }

    // ---- mainloop ----
    int fetch = NST - 1;
#pragma unroll 1
    for (int c = 0; c < KITER; c++) {
        asm volatile("cp.async.wait_group 2;");
        __syncthreads();

        if (fetch < KITER) {
            const uint32_t st = sb + (fetch & 3) * STAGE;
            const int k0 = fetch * 32;
#pragma unroll
            for (int j = 0; j < 2; j++) {
                cp16(st + sw_off[j],           g_xhi + a_goff[j] + k0);
                cp16(st + OFF_ALO + sw_off[j], g_xlo + a_goff[j] + k0);
                cp16(st + OFF_B + sw_off[j],   g_w1h + b_goff[j] + k0);
            }
        }
        asm volatile("cp.async.commit_group;");
        fetch++;

        const uint32_t st = sb + (c & 3) * STAGE;
#pragma unroll
        for (int kk = 0; kk < 2; kk++) {
            uint32_t ah[2][4], al[2][4], bfr[4][4];
#pragma unroll
            for (int mt = 0; mt < 2; mt++) {
                ldsm_x4(ah[mt], st + a_base[kk] + mt * 1024);
                ldsm_x4(al[mt], st + OFF_ALO + a_base[kk] + mt * 1024);
            }
#pragma unroll
            for (int nt2 = 0; nt2 < 4; nt2++)
                ldsm_x4(bfr[nt2], st + OFF_B + b_base[kk] + nt2 * 1024);
#pragma unroll
            for (int mt = 0; mt < 2; mt++)
#pragma unroll
                for (int nt = 0; nt < 8; nt++) {
                    const uint32_t* bp2 = &bfr[nt >> 1][(nt & 1) * 2];
                    mma16816(acc[mt][nt], ah[mt], bp2);
                    mma16816(acc[mt][nt], al[mt], bp2);
                }
        }
    }

    // ---- epilogue: bias + relu + store + max ----
    __shared__ float wmax[8];
    const int qrow  = lane >> 2;
    const int qcol2 = (lane & 3) * 2;
    float lmax = 0.0f;
#pragma unroll
    for (int mt = 0; mt < 2; mt++) {
#pragma unroll
        for (int nt = 0; nt < 8; nt++) {
            const int nl = warp_n * 64 + nt * 8 + qcol2;
            const int m0 = bm + warp_m * 32 + mt * 16 + qrow;
            const float bb0 = s_bias[nl], bb1 = s_bias[nl + 1];
            float v0 = fmaxf(acc[mt][nt][0] + bb0, 0.0f);
            float v1 = fmaxf(acc[mt][nt][1] + bb1, 0.0f);
            float v2 = fmaxf(acc[mt][nt][2] + bb0, 0.0f);
            float v3 = fmaxf(acc[mt][nt][3] + bb1, 0.0f);
            lmax = fmaxf(fmaxf(lmax, fmaxf(v0, v1)), fmaxf(v2, v3));
            float2 p0 = make_float2(v0, v1);
            float2 p1 = make_float2(v2, v3);
            *(float2*)(g_h + (size_t)m0 * D_H + bn + nl)       = p0;
            *(float2*)(g_h + (size_t)(m0 + 8) * D_H + bn + nl) = p1;
        }
    }
#pragma unroll
    for (int off = 16; off > 0; off >>= 1)
        lmax = fmaxf(lmax, __shfl_xor_sync(0xffffffffu, lmax, off));
    if (lane == 0) wmax[wid] = lmax;
    __syncthreads();
    if (tid == 0) {
        float m = wmax[0];
#pragma unroll
        for (int i = 1; i < 8; i++) m = fmaxf(m, wmax[i]);
        atomicMax(&g_maxbits, __float_as_uint(m));
    }
}

// ---------------- kernel 2: quant(int8) + dp4a layer2 + log_softmax ----------------
__global__ __launch_bounds__(256) void layer2_kernel(
    const float* __restrict__ b2,
    float* __restrict__ out)
{
    __shared__ int ws[D_OUT * (D_H / 4)];  // 40 KB packed int8 ternary w2

    const int tid = threadIdx.x;
#pragma unroll
    for (int i = 0; i < (D_OUT * (D_H / 4)) / 256; i++)
        ws[tid + i * 256] = g_w2q[tid + i * 256];
    __syncthreads();

    const float maxv  = __uint_as_float(g_maxbits);
    const float scale = 127.0f / maxv;

    const int lane = tid & 31, warp = tid >> 5;
    const int row  = blockIdx.x * 8 + warp;

    const float4* hrow = (const float4*)(g_h + (size_t)row * D_H);

    int acc[D_OUT];
#pragma unroll
    for (int c = 0; c < D_OUT; c++) acc[c] = 0;

#pragma unroll 4
    for (int it = lane; it < D_H / 4; it += 32) {
        float4 h4 = hrow[it];
        // h >= 0 after relu; clamp top side then round-to-nearest-even (matches jnp.round)
        int q0 = __float2int_rn(fminf(h4.x * scale, 127.0f));
        int q1 = __float2int_rn(fminf(h4.y * scale, 127.0f));
        int q2 = __float2int_rn(fminf(h4.z * scale, 127.0f));
        int q3 = __float2int_rn(fminf(h4.w * scale, 127.0f));
        int pk = (int)((uint32_t)q0 | ((uint32_t)q1 << 8) | ((uint32_t)q2 << 16) | ((uint32_t)q3 << 24));
#pragma unroll
        for (int c = 0; c < D_OUT; c++)
            acc[c] = dp4a_s(pk, ws[c * (D_H / 4) + it], acc[c]);
    }

    // warp reduce (exact integers)
#pragma unroll
    for (int off = 16; off > 0; off >>= 1)
#pragma unroll
        for (int c = 0; c < D_OUT; c++)
            acc[c] += __shfl_xor_sync(0xffffffffu, acc[c], off);

    if (lane == 0) {
        float l[D_OUT];
        float m = -1e30f;
#pragma unroll
        for (int c = 0; c < D_OUT; c++) {
            l[c] = (float)acc[c] / scale + b2[c];
            m = fmaxf(m, l[c]);
        }
        float s = 0.0f;
#pragma unroll
        for (int c = 0; c < D_OUT; c++) s += expf(l[c] - m);
        float lse = m + logf(s);
        float* orow = out + (size_t)row * D_OUT;
#pragma unroll
        for (int c = 0; c < D_OUT; c++) orow[c] = l[c] - lse;
    }
}

// ---------------- launch ----------------
extern "C" void kernel_launch(void* const* d_in, const int* in_sizes, int n_in,
                              void* d_out, int out_size)
{
    const float* x  = (const float*)d_in[0];
    const float* w1 = (const float*)d_in[1];
    const float* b1 = (const float*)d_in[2];
    const float* w2 = (const float*)d_in[3];
    const float* b2 = (const float*)d_in[4];
    float* out = (float*)d_out;

    cudaFuncSetAttribute(gemm1_mma_kernel, cudaFuncAttributeMaxDynamicSharedMemorySize, SMEM_REQ);

    prep_x_kernel<<<(B_ROWS * 104) / 256, 256>>>(x);         // also resets g_maxbits
    prep_w_kernel<<<(D_H * 104) / 256 + 1, 256>>>(w1, w2);   // w1 ternarize + w2 pack

    dim3 g1(D_H / 128, B_ROWS / 128);  // (32, 64)
    gemm1_mma_kernel<<<g1, 256, SMEM_REQ>>>(b1);

    layer2_kernel<<<B_ROWS / 8, 256>>>(b2, out);
}